// round 1
// baseline (speedup 1.0000x reference)
#include <cuda_runtime.h>
#include <cuda_bf16.h>
#include <cstdint>

#define DIN   4096
#define DOUT  4096
#define MROWS 16384
#define RNK   64

#define BM 128
#define BN 128
#define BK 32
#define PADK 40          // padded cols (bf16) per smem row -> 80B stride, ldmatrix conflict-free
#define STG_ELEMS (4*BM*PADK)   // 4 tiles (Xhi,Xlo,Whi,Wlo) of 128x40 bf16 per stage
#define TILE_ELEMS (BM*PADK)

// ---------------- scratch (static device globals; no allocation) ----------------
__device__ __nv_bfloat16 g_Whi[(size_t)DOUT*DIN];
__device__ __nv_bfloat16 g_Wlo[(size_t)DOUT*DIN];
__device__ __nv_bfloat16 g_Bhi[(size_t)DOUT*RNK];
__device__ __nv_bfloat16 g_Blo[(size_t)DOUT*RNK];
__device__ __nv_bfloat16 g_Zhi[(size_t)MROWS*RNK];
__device__ __nv_bfloat16 g_Zlo[(size_t)MROWS*RNK];

// ---------------- small PTX helpers ----------------
__device__ __forceinline__ uint32_t sptr(const void* p) {
    return (uint32_t)__cvta_generic_to_shared(p);
}
__device__ __forceinline__ void cp16(void* dst, const void* src) {
    asm volatile("cp.async.cg.shared.global [%0], [%1], 16;\n"
                 :: "r"(sptr(dst)), "l"(src));
}
__device__ __forceinline__ void cp_commit() {
    asm volatile("cp.async.commit_group;\n" ::);
}
template <int N>
__device__ __forceinline__ void cp_wait() {
    asm volatile("cp.async.wait_group %0;\n" :: "n"(N));
}
__device__ __forceinline__ void ldsm4(uint32_t* r, const void* p) {
    uint32_t a = sptr(p);
    asm volatile("ldmatrix.sync.aligned.m8n8.x4.shared.b16 {%0,%1,%2,%3}, [%4];\n"
                 : "=r"(r[0]), "=r"(r[1]), "=r"(r[2]), "=r"(r[3]) : "r"(a));
}
__device__ __forceinline__ void mma_bf16(float* c, const uint32_t* a, const uint32_t* b) {
    asm volatile(
        "mma.sync.aligned.m16n8k16.row.col.f32.bf16.bf16.f32 "
        "{%0,%1,%2,%3},{%4,%5,%6,%7},{%8,%9},{%0,%1,%2,%3};\n"
        : "+f"(c[0]), "+f"(c[1]), "+f"(c[2]), "+f"(c[3])
        : "r"(a[0]), "r"(a[1]), "r"(a[2]), "r"(a[3]), "r"(b[0]), "r"(b[1]));
}

// ---------------- kernel: split W into bf16 hi/lo ----------------
__global__ __launch_bounds__(256) void conv_w_kernel(const float* __restrict__ W) {
    size_t i = ((size_t)blockIdx.x * 256 + threadIdx.x) * 8;
    float4 v0 = *(const float4*)(W + i);
    float4 v1 = *(const float4*)(W + i + 4);
    float v[8] = {v0.x, v0.y, v0.z, v0.w, v1.x, v1.y, v1.z, v1.w};
#pragma unroll
    for (int j = 0; j < 8; j += 2) {
        __nv_bfloat162 h, l;
        h.x = __float2bfloat16(v[j]);
        h.y = __float2bfloat16(v[j + 1]);
        l.x = __float2bfloat16(v[j] - __bfloat162float(h.x));
        l.y = __float2bfloat16(v[j + 1] - __bfloat162float(h.y));
        *(__nv_bfloat162*)(g_Whi + i + j) = h;
        *(__nv_bfloat162*)(g_Wlo + i + j) = l;
    }
}

// ---------------- kernel: split B*SCALE into bf16 hi/lo ----------------
__global__ __launch_bounds__(256) void conv_b_kernel(const float* __restrict__ B, float scale) {
    size_t i = ((size_t)blockIdx.x * 256 + threadIdx.x) * 8;
    float4 v0 = *(const float4*)(B + i);
    float4 v1 = *(const float4*)(B + i + 4);
    float v[8] = {v0.x, v0.y, v0.z, v0.w, v1.x, v1.y, v1.z, v1.w};
#pragma unroll
    for (int j = 0; j < 8; j += 2) {
        float a = v[j] * scale, b = v[j + 1] * scale;
        __nv_bfloat162 h, l;
        h.x = __float2bfloat16(a);
        h.y = __float2bfloat16(b);
        l.x = __float2bfloat16(a - __bfloat162float(h.x));
        l.y = __float2bfloat16(b - __bfloat162float(h.y));
        *(__nv_bfloat162*)(g_Bhi + i + j) = h;
        *(__nv_bfloat162*)(g_Blo + i + j) = l;
    }
}

// ---------------- kernel: z = x @ A^T (fp32), topk mask, bf16 hi/lo split ----------------
__global__ __launch_bounds__(256) void z_topk_kernel(const float* __restrict__ x,
                                                     const float* __restrict__ A,
                                                     const int* __restrict__ kp) {
    __shared__ float Xs[64][65];
    __shared__ float As[64][65];
    const int t = threadIdx.x;
    const int mb = blockIdx.x * 64;
    float acc[4][4];
#pragma unroll
    for (int i = 0; i < 4; i++)
#pragma unroll
        for (int j = 0; j < 4; j++) acc[i][j] = 0.0f;

    const int m0 = (t >> 4) << 2;   // 0..60 step 4
    const int r0 = (t & 15) << 2;   // 0..60 step 4

    for (int kk = 0; kk < DIN; kk += 64) {
        const int row = t >> 2, cb = (t & 3) << 4;
#pragma unroll
        for (int i = 0; i < 4; i++) {
            float4 v = *(const float4*)(x + (size_t)(mb + row) * DIN + kk + cb + i * 4);
            Xs[row][cb + i * 4 + 0] = v.x;
            Xs[row][cb + i * 4 + 1] = v.y;
            Xs[row][cb + i * 4 + 2] = v.z;
            Xs[row][cb + i * 4 + 3] = v.w;
            float4 w = *(const float4*)(A + (size_t)row * DIN + kk + cb + i * 4);
            As[row][cb + i * 4 + 0] = w.x;
            As[row][cb + i * 4 + 1] = w.y;
            As[row][cb + i * 4 + 2] = w.z;
            As[row][cb + i * 4 + 3] = w.w;
        }
        __syncthreads();
#pragma unroll 8
        for (int k2 = 0; k2 < 64; k2++) {
            float xa[4], ar[4];
#pragma unroll
            for (int i = 0; i < 4; i++) xa[i] = Xs[m0 + i][k2];
#pragma unroll
            for (int j = 0; j < 4; j++) ar[j] = As[r0 + j][k2];
#pragma unroll
            for (int i = 0; i < 4; i++)
#pragma unroll
                for (int j = 0; j < 4; j++) acc[i][j] = fmaf(xa[i], ar[j], acc[i][j]);
        }
        __syncthreads();
    }

    // stash z rows (reuse Xs), then top-k mask via strictly-greater count
    float(*zs)[65] = Xs;
#pragma unroll
    for (int i = 0; i < 4; i++)
#pragma unroll
        for (int j = 0; j < 4; j++) zs[m0 + i][r0 + j] = acc[i][j];
    __syncthreads();

    const int kkeep = *kp;
#pragma unroll
    for (int e = 0; e < 16; e++) {
        int idx = e * 256 + t;
        int row = idx >> 6, rr = idx & 63;
        float zv = zs[row][rr];
        float az = fabsf(zv);
        int cnt = 0;
#pragma unroll
        for (int j = 0; j < 64; j++) cnt += (fabsf(zs[row][j]) > az) ? 1 : 0;
        float zm = (cnt < kkeep) ? zv : 0.0f;   // matches az >= thresh incl. ties
        __nv_bfloat16 h = __float2bfloat16(zm);
        float lo = zm - __bfloat162float(h);
        size_t gi = (size_t)(mb + row) * RNK + rr;
        g_Zhi[gi] = h;
        g_Zlo[gi] = __float2bfloat16(lo);
    }
}

// ---------------- main fused GEMM helpers ----------------
__device__ __forceinline__ void ldg_x(float4* fr, const float* __restrict__ x,
                                      int bm, int kk, int t) {
    const int r = t >> 1, half = t & 1;
    const float* p = x + (size_t)(bm + r) * DIN + kk + half * 16;
    fr[0] = *(const float4*)(p);
    fr[1] = *(const float4*)(p + 4);
    fr[2] = *(const float4*)(p + 8);
    fr[3] = *(const float4*)(p + 12);
}

__device__ __forceinline__ void sts_x(const float4* fr, __nv_bfloat16* sXhi,
                                      __nv_bfloat16* sXlo, int t) {
    const int r = t >> 1, half = t & 1;
    const int off = r * PADK + half * 16;
#pragma unroll
    for (int i = 0; i < 4; i++) {
        float a = fr[i].x, b = fr[i].y, c = fr[i].z, d = fr[i].w;
        __nv_bfloat162 h01, h23, l01, l23;
        h01.x = __float2bfloat16(a);
        h01.y = __float2bfloat16(b);
        h23.x = __float2bfloat16(c);
        h23.y = __float2bfloat16(d);
        l01.x = __float2bfloat16(a - __bfloat162float(h01.x));
        l01.y = __float2bfloat16(b - __bfloat162float(h01.y));
        l23.x = __float2bfloat16(c - __bfloat162float(h23.x));
        l23.y = __float2bfloat16(d - __bfloat162float(h23.y));
        *(__nv_bfloat162*)(sXhi + off + i * 4)     = h01;
        *(__nv_bfloat162*)(sXhi + off + i * 4 + 2) = h23;
        *(__nv_bfloat162*)(sXlo + off + i * 4)     = l01;
        *(__nv_bfloat162*)(sXlo + off + i * 4 + 2) = l23;
    }
}

// async-copy a 128-row x 32-col bf16 tile pair (hi/lo) with arbitrary row stride
__device__ __forceinline__ void issue_w(__nv_bfloat16* sWhi, __nv_bfloat16* sWlo,
                                        const __nv_bfloat16* __restrict__ ghi,
                                        const __nv_bfloat16* __restrict__ glo,
                                        int bn, int kk, int stride, int t) {
#pragma unroll
    for (int j = 0; j < 2; j++) {
        int c = t + j * 256;            // 0..511
        int row = c >> 2, part = c & 3; // 4x16B chunks per row
        size_t src = (size_t)(bn + row) * stride + kk + part * 8;
        cp16(sWhi + row * PADK + part * 8, ghi + src);
        cp16(sWlo + row * PADK + part * 8, glo + src);
    }
}

// async-copy the z (bf16 hi/lo) "A-operand" tile for the LoRA K-extension
__device__ __forceinline__ void issue_zx(__nv_bfloat16* sXhi, __nv_bfloat16* sXlo,
                                         int bm, int kk, int t) {
    const int r = t >> 1, half = t & 1;
    size_t src = (size_t)(bm + r) * RNK + kk + half * 16;
    cp16(sXhi + r * PADK + half * 16,     g_Zhi + src);
    cp16(sXhi + r * PADK + half * 16 + 8, g_Zhi + src + 8);
    cp16(sXlo + r * PADK + half * 16,     g_Zlo + src);
    cp16(sXlo + r * PADK + half * 16 + 8, g_Zlo + src + 8);
}

__device__ __forceinline__ void compute_tile(float acc[4][4][4],
                                             const __nv_bfloat16* sXhi,
                                             const __nv_bfloat16* sXlo,
                                             const __nv_bfloat16* sWhi,
                                             const __nv_bfloat16* sWlo,
                                             int wm, int wn, int lane) {
#pragma unroll
    for (int ks = 0; ks < 2; ks++) {
        uint32_t ahi[4][4], alo[4][4], bhi[2][4], blo[2][4];
        const int arow = wm * 64 + (lane & 15);
        const int acol = ks * 16 + (lane >> 4) * 8;
#pragma unroll
        for (int mt = 0; mt < 4; mt++) {
            ldsm4(ahi[mt], sXhi + (arow + mt * 16) * PADK + acol);
            ldsm4(alo[mt], sXlo + (arow + mt * 16) * PADK + acol);
        }
        const int brow = wn * 32 + ((lane >> 4) << 3) + (lane & 7);
        const int bcol = ks * 16 + (((lane >> 3) & 1) << 3);
#pragma unroll
        for (int np = 0; np < 2; np++) {
            ldsm4(bhi[np], sWhi + (brow + np * 16) * PADK + bcol);
            ldsm4(blo[np], sWlo + (brow + np * 16) * PADK + bcol);
        }
#pragma unroll
        for (int mt = 0; mt < 4; mt++)
#pragma unroll
            for (int nt = 0; nt < 4; nt++) {
                const uint32_t* bh = &bhi[nt >> 1][(nt & 1) * 2];
                const uint32_t* bl = &blo[nt >> 1][(nt & 1) * 2];
                mma_bf16(acc[mt][nt], ahi[mt], bh);  // xhi * Whi
                mma_bf16(acc[mt][nt], ahi[mt], bl);  // xhi * Wlo
                mma_bf16(acc[mt][nt], alo[mt], bh);  // xlo * Whi
            }
    }
}

// ---------------- main fused kernel: out = x@W^T + b + z_sparse@(B*SCALE)^T ----------------
__global__ __launch_bounds__(256, 1)
void gemm_kernel(const float* __restrict__ x, const float* __restrict__ bias,
                 float* __restrict__ out) {
    extern __shared__ __nv_bfloat16 sm[];
    const int t = threadIdx.x;
    const int warp = t >> 5, lane = t & 31;
    const int wm = warp & 1, wn = warp >> 1;  // 2 x 4 warp grid -> 64x32 warp tile
    const int bm = blockIdx.y * BM, bn = blockIdx.x * BN;

    float acc[4][4][4];
#pragma unroll
    for (int a = 0; a < 4; a++)
#pragma unroll
        for (int b = 0; b < 4; b++)
#pragma unroll
            for (int c = 0; c < 4; c++) acc[a][b][c] = 0.0f;

    __nv_bfloat16* st0 = sm;
    __nv_bfloat16* st1 = sm + STG_ELEMS;

    float4 fr[4];
    const int NMAIN = DIN / BK;  // 128

    // prologue: fill both stages
    ldg_x(fr, x, bm, 0, t);
    sts_x(fr, st0, st0 + TILE_ELEMS, t);
    issue_w(st0 + 2 * TILE_ELEMS, st0 + 3 * TILE_ELEMS, g_Whi, g_Wlo, bn, 0, DIN, t);
    cp_commit();
    ldg_x(fr, x, bm, BK, t);
    sts_x(fr, st1, st1 + TILE_ELEMS, t);
    issue_w(st1 + 2 * TILE_ELEMS, st1 + 3 * TILE_ELEMS, g_Whi, g_Wlo, bn, BK, DIN, t);
    cp_commit();

    for (int i = 0; i < NMAIN; i++) {
        __nv_bfloat16* st = (i & 1) ? st1 : st0;
        const bool pre = (i + 2) < NMAIN;
        if (pre) ldg_x(fr, x, bm, (i + 2) * BK, t);  // LDG early; consumed post-compute
        if (i + 1 < NMAIN) cp_wait<1>(); else cp_wait<0>();
        __syncthreads();
        compute_tile(acc, st, st + TILE_ELEMS, st + 2 * TILE_ELEMS, st + 3 * TILE_ELEMS,
                     wm, wn, lane);
        __syncthreads();
        if (pre) {
            sts_x(fr, st, st + TILE_ELEMS, t);
            issue_w(st + 2 * TILE_ELEMS, st + 3 * TILE_ELEMS, g_Whi, g_Wlo,
                    bn, (i + 2) * BK, DIN, t);
            cp_commit();
        }
    }

    // LoRA K-extension: 2 x BK=32 chunks over R=64 (z hi/lo vs B'=B*SCALE hi/lo)
    issue_zx(st0, st0 + TILE_ELEMS, bm, 0, t);
    issue_w(st0 + 2 * TILE_ELEMS, st0 + 3 * TILE_ELEMS, g_Bhi, g_Blo, bn, 0, RNK, t);
    cp_commit();
    issue_zx(st1, st1 + TILE_ELEMS, bm, 32, t);
    issue_w(st1 + 2 * TILE_ELEMS, st1 + 3 * TILE_ELEMS, g_Bhi, g_Blo, bn, 32, RNK, t);
    cp_commit();
    cp_wait<1>();
    __syncthreads();
    compute_tile(acc, st0, st0 + TILE_ELEMS, st0 + 2 * TILE_ELEMS, st0 + 3 * TILE_ELEMS,
                 wm, wn, lane);
    cp_wait<0>();
    __syncthreads();
    compute_tile(acc, st1, st1 + TILE_ELEMS, st1 + 2 * TILE_ELEMS, st1 + 3 * TILE_ELEMS,
                 wm, wn, lane);

    // epilogue: + bias, store fp32
    const int gr = lane >> 2, gc = (lane & 3) * 2;
#pragma unroll
    for (int mt = 0; mt < 4; mt++) {
#pragma unroll
        for (int nt = 0; nt < 4; nt++) {
            int row = bm + wm * 64 + mt * 16 + gr;
            int col = bn + wn * 32 + nt * 8 + gc;
            float2 bv = *(const float2*)(bias + col);
            float2 o0, o1;
            o0.x = acc[mt][nt][0] + bv.x;
            o0.y = acc[mt][nt][1] + bv.y;
            o1.x = acc[mt][nt][2] + bv.x;
            o1.y = acc[mt][nt][3] + bv.y;
            *(float2*)(out + (size_t)row * DOUT + col) = o0;
            *(float2*)(out + (size_t)(row + 8) * DOUT + col) = o1;
        }
    }
}

// ---------------- launch ----------------
extern "C" void kernel_launch(void* const* d_in, const int* in_sizes, int n_in,
                              void* d_out, int out_size) {
    const float* x = (const float*)d_in[0];
    const float* W = (const float*)d_in[1];
    const float* b = (const float*)d_in[2];
    const float* A = (const float*)d_in[3];
    const float* B = (const float*)d_in[4];
    const int*   k = (const int*)d_in[5];
    float* out = (float*)d_out;

    (void)in_sizes; (void)n_in; (void)out_size;

    // split W, B*SCALE into bf16 hi/lo (deterministic; replayed every graph launch)
    conv_w_kernel<<<(DOUT * DIN) / (256 * 8), 256>>>(W);
    conv_b_kernel<<<(DOUT * RNK) / (256 * 8), 256>>>(B, 2.0f /* ALPHA/R */);

    // z = x @ A^T in fp32, top-k mask, split to bf16 hi/lo
    z_topk_kernel<<<MROWS / 64, 256>>>(x, A, k);

    // fused: out = x@W^T + b + z@(B*SCALE)^T  (split-bf16 3-pass emulation)
    cudaFuncSetAttribute(gemm_kernel, cudaFuncAttributeMaxDynamicSharedMemorySize,
                         2 * STG_ELEMS * (int)sizeof(__nv_bfloat16));
    gemm_kernel<<<dim3(DOUT / BN, MROWS / BM), 256,
                  2 * STG_ELEMS * sizeof(__nv_bfloat16)>>>(x, b, out);
}

// round 3
// speedup vs baseline: 1.2703x; 1.2703x over previous
#include <cuda_runtime.h>
#include <cuda_bf16.h>
#include <cstdint>

#define DIN   4096
#define DOUT  4096
#define MROWS 16384
#define RNK   64

#define BM 128
#define BN 128
#define BK 32
#define PADK 40                      // bf16 elems per smem row (80B) -> ldmatrix conflict-free
#define TILE_BYTES (BM*PADK*2)       // 10240 B per tile
#define STG_BYTES  (4*TILE_BYTES)    // Xhi, Xlo, Whi, Wlo = 40 KB per stage
#define NSTAGE 4
#define NIT_MAIN (DIN/BK)            // 128
#define NIT (NIT_MAIN + RNK/BK)      // 130 (2 LoRA chunks)

// ---------------- scratch (static device globals; no allocation) ----------------
__device__ __nv_bfloat16 g_Whi[(size_t)DOUT*DIN];
__device__ __nv_bfloat16 g_Wlo[(size_t)DOUT*DIN];
__device__ __nv_bfloat16 g_Xhi[(size_t)MROWS*DIN];
__device__ __nv_bfloat16 g_Xlo[(size_t)MROWS*DIN];
__device__ __nv_bfloat16 g_Bhi[(size_t)DOUT*RNK];
__device__ __nv_bfloat16 g_Blo[(size_t)DOUT*RNK];
__device__ __nv_bfloat16 g_Zhi[(size_t)MROWS*RNK];
__device__ __nv_bfloat16 g_Zlo[(size_t)MROWS*RNK];

// ---------------- PTX helpers ----------------
__device__ __forceinline__ uint32_t sptr(const void* p) {
    return (uint32_t)__cvta_generic_to_shared(p);
}
__device__ __forceinline__ void cp16s(uint32_t dst, const void* src) {
    asm volatile("cp.async.cg.shared.global [%0], [%1], 16;" :: "r"(dst), "l"(src));
}
__device__ __forceinline__ void cp_commit() { asm volatile("cp.async.commit_group;" ::); }
template <int N> __device__ __forceinline__ void cp_wait() {
    asm volatile("cp.async.wait_group %0;" :: "n"(N));
}
__device__ __forceinline__ void ldsm4(uint32_t* r, uint32_t a) {
    asm volatile("ldmatrix.sync.aligned.m8n8.x4.shared.b16 {%0,%1,%2,%3}, [%4];"
                 : "=r"(r[0]), "=r"(r[1]), "=r"(r[2]), "=r"(r[3]) : "r"(a));
}
__device__ __forceinline__ void mma_bf16(float* c, const uint32_t* a, const uint32_t* b) {
    asm volatile(
        "mma.sync.aligned.m16n8k16.row.col.f32.bf16.bf16.f32 "
        "{%0,%1,%2,%3},{%4,%5,%6,%7},{%8,%9},{%0,%1,%2,%3};\n"
        : "+f"(c[0]), "+f"(c[1]), "+f"(c[2]), "+f"(c[3])
        : "r"(a[0]), "r"(a[1]), "r"(a[2]), "r"(a[3]), "r"(b[0]), "r"(b[1]));
}

// ---------------- split kernels: fp32 -> bf16 hi/lo ----------------
__device__ __forceinline__ void split8(const float* __restrict__ src, size_t i,
                                       __nv_bfloat16* __restrict__ hi,
                                       __nv_bfloat16* __restrict__ lo, float scale) {
    float4 v0 = *(const float4*)(src + i);
    float4 v1 = *(const float4*)(src + i + 4);
    float v[8] = {v0.x, v0.y, v0.z, v0.w, v1.x, v1.y, v1.z, v1.w};
#pragma unroll
    for (int j = 0; j < 8; j += 2) {
        float a = v[j] * scale, b = v[j + 1] * scale;
        __nv_bfloat162 h, l;
        h.x = __float2bfloat16(a);
        h.y = __float2bfloat16(b);
        l.x = __float2bfloat16(a - __bfloat162float(h.x));
        l.y = __float2bfloat16(b - __bfloat162float(h.y));
        *(__nv_bfloat162*)(hi + i + j) = h;
        *(__nv_bfloat162*)(lo + i + j) = l;
    }
}
__global__ __launch_bounds__(256) void conv_w_kernel(const float* __restrict__ W) {
    size_t i = ((size_t)blockIdx.x * 256 + threadIdx.x) * 8;
    split8(W, i, g_Whi, g_Wlo, 1.0f);
}
__global__ __launch_bounds__(256) void conv_x_kernel(const float* __restrict__ x) {
    size_t i = ((size_t)blockIdx.x * 256 + threadIdx.x) * 8;
    split8(x, i, g_Xhi, g_Xlo, 1.0f);
}
__global__ __launch_bounds__(256) void conv_b_kernel(const float* __restrict__ B, float scale) {
    size_t i = ((size_t)blockIdx.x * 256 + threadIdx.x) * 8;
    split8(B, i, g_Bhi, g_Blo, scale);
}

// ---------------- z = x @ A^T (fp32), top-k mask, bf16 hi/lo split ----------------
__global__ __launch_bounds__(256) void z_topk_kernel(const float* __restrict__ x,
                                                     const float* __restrict__ A,
                                                     const int* __restrict__ kp) {
    __shared__ float Xs[64][65];
    __shared__ float As[64][65];
    const int t = threadIdx.x;
    const int mb = blockIdx.x * 64;
    float acc[4][4];
#pragma unroll
    for (int i = 0; i < 4; i++)
#pragma unroll
        for (int j = 0; j < 4; j++) acc[i][j] = 0.0f;

    const int m0 = (t >> 4) << 2;
    const int r0 = (t & 15) << 2;

    for (int kk = 0; kk < DIN; kk += 64) {
        const int row = t >> 2, cb = (t & 3) << 4;
#pragma unroll
        for (int i = 0; i < 4; i++) {
            float4 v = *(const float4*)(x + (size_t)(mb + row) * DIN + kk + cb + i * 4);
            Xs[row][cb + i * 4 + 0] = v.x;
            Xs[row][cb + i * 4 + 1] = v.y;
            Xs[row][cb + i * 4 + 2] = v.z;
            Xs[row][cb + i * 4 + 3] = v.w;
            float4 w = *(const float4*)(A + (size_t)row * DIN + kk + cb + i * 4);
            As[row][cb + i * 4 + 0] = w.x;
            As[row][cb + i * 4 + 1] = w.y;
            As[row][cb + i * 4 + 2] = w.z;
            As[row][cb + i * 4 + 3] = w.w;
        }
        __syncthreads();
#pragma unroll 8
        for (int k2 = 0; k2 < 64; k2++) {
            float xa[4], ar[4];
#pragma unroll
            for (int i = 0; i < 4; i++) xa[i] = Xs[m0 + i][k2];
#pragma unroll
            for (int j = 0; j < 4; j++) ar[j] = As[r0 + j][k2];
#pragma unroll
            for (int i = 0; i < 4; i++)
#pragma unroll
                for (int j = 0; j < 4; j++) acc[i][j] = fmaf(xa[i], ar[j], acc[i][j]);
        }
        __syncthreads();
    }

    float(*zs)[65] = Xs;
#pragma unroll
    for (int i = 0; i < 4; i++)
#pragma unroll
        for (int j = 0; j < 4; j++) zs[m0 + i][r0 + j] = acc[i][j];
    __syncthreads();

    const int kkeep = *kp;
#pragma unroll
    for (int e = 0; e < 16; e++) {
        int idx = e * 256 + t;
        int row = idx >> 6, rr = idx & 63;
        float zv = zs[row][rr];
        float az = fabsf(zv);
        int cnt = 0;
#pragma unroll
        for (int j = 0; j < 64; j++) cnt += (fabsf(zs[row][j]) > az) ? 1 : 0;
        float zm = (cnt < kkeep) ? zv : 0.0f;
        __nv_bfloat16 h = __float2bfloat16(zm);
        float lo = zm - __bfloat162float(h);
        size_t gi = (size_t)(mb + row) * RNK + rr;
        g_Zhi[gi] = h;
        g_Zlo[gi] = __float2bfloat16(lo);
    }
}

// ---------------- main GEMM: out = x@W^T + b + z_sparse@(B*SCALE)^T ----------------
// Fully cp.async-fed 4-stage pipeline; all operands pre-split bf16 in GMEM.

// fill one stage (4 tiles of 128x32 bf16) for chunk index i
__device__ __forceinline__ void issue_stage(uint32_t stg, int bm, int bn, int i, int t) {
    const __nv_bfloat16 *pah, *pal, *pbh, *pbl;
    int stride;
    if (i < NIT_MAIN) {
        const int kk = i * BK;
        pah = g_Xhi + (size_t)bm * DIN + kk;
        pal = g_Xlo + (size_t)bm * DIN + kk;
        pbh = g_Whi + (size_t)bn * DIN + kk;
        pbl = g_Wlo + (size_t)bn * DIN + kk;
        stride = DIN;
    } else {
        const int kk = (i - NIT_MAIN) * BK;
        pah = g_Zhi + (size_t)bm * RNK + kk;
        pal = g_Zlo + (size_t)bm * RNK + kk;
        pbh = g_Bhi + (size_t)bn * RNK + kk;
        pbl = g_Blo + (size_t)bn * RNK + kk;
        stride = RNK;
    }
#pragma unroll
    for (int j = 0; j < 2; j++) {
        const int idx = t + j * 256;               // 0..511
        const int row = idx >> 2, part = idx & 3;  // 128 rows x 4 16B chunks
        const uint32_t d = (uint32_t)(row * PADK + part * 8) * 2;  // byte offset
        const size_t s = (size_t)row * stride + part * 8;
        cp16s(stg + d,                  pah + s);
        cp16s(stg + TILE_BYTES + d,     pal + s);
        cp16s(stg + 2 * TILE_BYTES + d, pbh + s);
        cp16s(stg + 3 * TILE_BYTES + d, pbl + s);
    }
}

__device__ __forceinline__ void compute_tile(float acc[4][4][4], uint32_t stg,
                                             int wm, int wn, int lane) {
    const uint32_t sXhi = stg, sXlo = stg + TILE_BYTES;
    const uint32_t sWhi = stg + 2 * TILE_BYTES, sWlo = stg + 3 * TILE_BYTES;
#pragma unroll
    for (int ks = 0; ks < 2; ks++) {
        uint32_t ahi[4][4], alo[4][4], bhi[2][4], blo[2][4];
        const int arow = wm * 64 + (lane & 15);
        const int acol = ks * 16 + (lane >> 4) * 8;
#pragma unroll
        for (int mt = 0; mt < 4; mt++) {
            const uint32_t off = (uint32_t)((arow + mt * 16) * PADK + acol) * 2;
            ldsm4(ahi[mt], sXhi + off);
            ldsm4(alo[mt], sXlo + off);
        }
        const int brow = wn * 32 + ((lane >> 4) << 3) + (lane & 7);
        const int bcol = ks * 16 + (((lane >> 3) & 1) << 3);
#pragma unroll
        for (int np = 0; np < 2; np++) {
            const uint32_t off = (uint32_t)((brow + np * 16) * PADK + bcol) * 2;
            ldsm4(bhi[np], sWhi + off);
            ldsm4(blo[np], sWlo + off);
        }
#pragma unroll
        for (int mt = 0; mt < 4; mt++)
#pragma unroll
            for (int nt = 0; nt < 4; nt++) {
                const uint32_t* bh = &bhi[nt >> 1][(nt & 1) * 2];
                const uint32_t* bl = &blo[nt >> 1][(nt & 1) * 2];
                mma_bf16(acc[mt][nt], ahi[mt], bh);  // xhi * Whi
                mma_bf16(acc[mt][nt], ahi[mt], bl);  // xhi * Wlo
                mma_bf16(acc[mt][nt], alo[mt], bh);  // xlo * Whi
            }
    }
}

__global__ __launch_bounds__(256, 1)
void gemm_kernel(const float* __restrict__ bias, float* __restrict__ out) {
    extern __shared__ __nv_bfloat16 smem[];
    const uint32_t sb = sptr(smem);
    const int t = threadIdx.x;
    const int warp = t >> 5, lane = t & 31;
    const int wm = warp & 1, wn = warp >> 1;   // 2x4 warp grid -> 64x32 warp tile
    const int bm = (int)blockIdx.y * BM, bn = (int)blockIdx.x * BN;

    float acc[4][4][4];
#pragma unroll
    for (int a = 0; a < 4; a++)
#pragma unroll
        for (int b = 0; b < 4; b++)
#pragma unroll
            for (int c = 0; c < 4; c++) acc[a][b][c] = 0.0f;

    // prologue: fill stages 0..2
#pragma unroll
    for (int i = 0; i < NSTAGE - 1; i++) {
        issue_stage(sb + i * STG_BYTES, bm, bn, i, t);
        cp_commit();
    }

    for (int i = 0; i < NIT; i++) {
        cp_wait<NSTAGE - 2>();   // group i (stage i%4) complete
        __syncthreads();
        const uint32_t stg = sb + (i % NSTAGE) * STG_BYTES;
        compute_tile(acc, stg, wm, wn, lane);
        if (i + NSTAGE - 1 < NIT)
            issue_stage(sb + ((i + NSTAGE - 1) % NSTAGE) * STG_BYTES, bm, bn,
                        i + NSTAGE - 1, t);
        cp_commit();             // commit every iter (possibly empty) to keep accounting
    }

    // epilogue: + bias, store fp32
    const int gr = lane >> 2, gc = (lane & 3) * 2;
#pragma unroll
    for (int mt = 0; mt < 4; mt++) {
#pragma unroll
        for (int nt = 0; nt < 4; nt++) {
            int row = bm + wm * 64 + mt * 16 + gr;
            int col = bn + wn * 32 + nt * 8 + gc;
            float2 bv = *(const float2*)(bias + col);
            float2 o0, o1;
            o0.x = acc[mt][nt][0] + bv.x;
            o0.y = acc[mt][nt][1] + bv.y;
            o1.x = acc[mt][nt][2] + bv.x;
            o1.y = acc[mt][nt][3] + bv.y;
            *(float2*)(out + (size_t)row * DOUT + col) = o0;
            *(float2*)(out + (size_t)(row + 8) * DOUT + col) = o1;
        }
    }
}

// ---------------- launch ----------------
extern "C" void kernel_launch(void* const* d_in, const int* in_sizes, int n_in,
                              void* d_out, int out_size) {
    const float* x = (const float*)d_in[0];
    const float* W = (const float*)d_in[1];
    const float* b = (const float*)d_in[2];
    const float* A = (const float*)d_in[3];
    const float* B = (const float*)d_in[4];
    const int*   k = (const int*)d_in[5];
    float* out = (float*)d_out;
    (void)in_sizes; (void)n_in; (void)out_size;

    // split inputs to bf16 hi/lo
    conv_w_kernel<<<(DOUT * DIN) / (256 * 8), 256>>>(W);
    conv_x_kernel<<<(int)(((size_t)MROWS * DIN) / (256 * 8)), 256>>>(x);
    conv_b_kernel<<<(DOUT * RNK) / (256 * 8), 256>>>(B, 2.0f /* ALPHA/R */);

    // z = x @ A^T in fp32, top-k mask, split to bf16 hi/lo
    z_topk_kernel<<<MROWS / 64, 256>>>(x, A, k);

    // fused GEMM (split-bf16 3-pass emulation, fully async-fed)
    cudaFuncSetAttribute(gemm_kernel, cudaFuncAttributeMaxDynamicSharedMemorySize,
                         NSTAGE * STG_BYTES);
    gemm_kernel<<<dim3(DOUT / BN, MROWS / BM), 256, NSTAGE * STG_BYTES>>>(b, out);
}

// round 4
// speedup vs baseline: 1.4347x; 1.1294x over previous
#include <cuda_runtime.h>
#include <cuda_bf16.h>
#include <cstdint>

#define DIN   4096
#define DOUT  4096
#define MROWS 16384
#define RNK   64

#define BM 128
#define BN 256
#define BK 32
#define PADK 40                        // bf16 elems per smem row (80B), ldmatrix conflict-free
#define XT_BYTES (BM*PADK*2)           // 10240 B  (128-row tile)
#define WT_BYTES (BN*PADK*2)           // 20480 B  (256-row tile)
#define STG_BYTES (2*XT_BYTES + 2*WT_BYTES)   // 61440 B per stage
#define NSTAGE 3
#define NIT_MAIN (DIN/BK)              // 128
#define NIT (NIT_MAIN + RNK/BK)        // 130

// ---------------- scratch (static device globals; no allocation) ----------------
__device__ __nv_bfloat16 g_Whi[(size_t)DOUT*DIN];
__device__ __nv_bfloat16 g_Wlo[(size_t)DOUT*DIN];
__device__ __nv_bfloat16 g_Xhi[(size_t)MROWS*DIN];
__device__ __nv_bfloat16 g_Xlo[(size_t)MROWS*DIN];
__device__ __nv_bfloat16 g_Ahi[(size_t)RNK*DIN];
__device__ __nv_bfloat16 g_Alo[(size_t)RNK*DIN];
__device__ __nv_bfloat16 g_Bhi[(size_t)DOUT*RNK];
__device__ __nv_bfloat16 g_Blo[(size_t)DOUT*RNK];
__device__ __nv_bfloat16 g_Zhi[(size_t)MROWS*RNK];
__device__ __nv_bfloat16 g_Zlo[(size_t)MROWS*RNK];

// ---------------- PTX helpers ----------------
__device__ __forceinline__ uint32_t sptr(const void* p) {
    return (uint32_t)__cvta_generic_to_shared(p);
}
__device__ __forceinline__ void cp16s(uint32_t dst, const void* src) {
    asm volatile("cp.async.cg.shared.global [%0], [%1], 16;" :: "r"(dst), "l"(src));
}
__device__ __forceinline__ void cp_commit() { asm volatile("cp.async.commit_group;" ::); }
template <int N> __device__ __forceinline__ void cp_wait() {
    asm volatile("cp.async.wait_group %0;" :: "n"(N));
}
__device__ __forceinline__ void ldsm4(uint32_t* r, uint32_t a) {
    asm volatile("ldmatrix.sync.aligned.m8n8.x4.shared.b16 {%0,%1,%2,%3}, [%4];"
                 : "=r"(r[0]), "=r"(r[1]), "=r"(r[2]), "=r"(r[3]) : "r"(a));
}
__device__ __forceinline__ void mma_bf16(float* c, const uint32_t* a, const uint32_t* b) {
    asm volatile(
        "mma.sync.aligned.m16n8k16.row.col.f32.bf16.bf16.f32 "
        "{%0,%1,%2,%3},{%4,%5,%6,%7},{%8,%9},{%0,%1,%2,%3};\n"
        : "+f"(c[0]), "+f"(c[1]), "+f"(c[2]), "+f"(c[3])
        : "r"(a[0]), "r"(a[1]), "r"(a[2]), "r"(a[3]), "r"(b[0]), "r"(b[1]));
}

// ---------------- split kernels: fp32 -> bf16 hi/lo ----------------
__device__ __forceinline__ void split8(const float* __restrict__ src, size_t i,
                                       __nv_bfloat16* __restrict__ hi,
                                       __nv_bfloat16* __restrict__ lo, float scale) {
    float4 v0 = *(const float4*)(src + i);
    float4 v1 = *(const float4*)(src + i + 4);
    float v[8] = {v0.x, v0.y, v0.z, v0.w, v1.x, v1.y, v1.z, v1.w};
#pragma unroll
    for (int j = 0; j < 8; j += 2) {
        float a = v[j] * scale, b = v[j + 1] * scale;
        __nv_bfloat162 h, l;
        h.x = __float2bfloat16(a);
        h.y = __float2bfloat16(b);
        l.x = __float2bfloat16(a - __bfloat162float(h.x));
        l.y = __float2bfloat16(b - __bfloat162float(h.y));
        *(__nv_bfloat162*)(hi + i + j) = h;
        *(__nv_bfloat162*)(lo + i + j) = l;
    }
}
__global__ __launch_bounds__(256) void conv_w_kernel(const float* __restrict__ W) {
    size_t i = ((size_t)blockIdx.x * 256 + threadIdx.x) * 8;
    split8(W, i, g_Whi, g_Wlo, 1.0f);
}
__global__ __launch_bounds__(256) void conv_x_kernel(const float* __restrict__ x) {
    size_t i = ((size_t)blockIdx.x * 256 + threadIdx.x) * 8;
    split8(x, i, g_Xhi, g_Xlo, 1.0f);
}
__global__ __launch_bounds__(256) void conv_a_kernel(const float* __restrict__ A) {
    size_t i = ((size_t)blockIdx.x * 256 + threadIdx.x) * 8;
    split8(A, i, g_Ahi, g_Alo, 1.0f);
}
__global__ __launch_bounds__(256) void conv_b_kernel(const float* __restrict__ B, float scale) {
    size_t i = ((size_t)blockIdx.x * 256 + threadIdx.x) * 8;
    split8(B, i, g_Bhi, g_Blo, scale);
}

// ================= z kernel: z = x@A^T via HMMA, top-k mask, bf16 split =================
// BM=128 rows, all 64 ranks. 8 warps, 2x4 grid -> warp tile 64x16.
#define ZXT 10240                      // 128x40 bf16
#define ZAT 5120                       // 64x40 bf16
#define ZSTG (2*ZXT + 2*ZAT)           // 30720
#define ZPAD 66

__device__ __forceinline__ void z_issue(uint32_t stg, int bm, int i, int t) {
    const int kk = i * BK;
    const __nv_bfloat16* px = g_Xhi + (size_t)bm * DIN + kk;
    const __nv_bfloat16* pl = g_Xlo + (size_t)bm * DIN + kk;
#pragma unroll
    for (int j = 0; j < 2; j++) {
        const int idx = t + j * 256;               // 0..511
        const int row = idx >> 2, part = idx & 3;
        const uint32_t d = (uint32_t)(row * PADK + part * 8) * 2;
        const size_t s = (size_t)row * DIN + part * 8;
        cp16s(stg + d,            px + s);
        cp16s(stg + ZXT + d,      pl + s);
    }
    {   // A tiles: 64 rows x 4 parts = 256 positions
        const int row = t >> 2, part = t & 3;
        const uint32_t d = (uint32_t)(row * PADK + part * 8) * 2;
        const size_t s = (size_t)row * DIN + kk + part * 8;
        cp16s(stg + 2 * ZXT + d,       g_Ahi + s);
        cp16s(stg + 2 * ZXT + ZAT + d, g_Alo + s);
    }
}

__global__ __launch_bounds__(256, 1)
void z_mma_topk_kernel(const int* __restrict__ kp) {
    extern __shared__ char zsm[];
    const uint32_t sb = sptr(zsm);
    const int t = threadIdx.x, warp = t >> 5, lane = t & 31;
    const int wm = warp & 1, wn = warp >> 1;    // 64x16 warp tile
    const int bm = (int)blockIdx.x * BM;

    float acc[4][2][4];
#pragma unroll
    for (int a = 0; a < 4; a++)
#pragma unroll
        for (int b = 0; b < 2; b++)
#pragma unroll
            for (int c = 0; c < 4; c++) acc[a][b][c] = 0.0f;

#pragma unroll
    for (int i = 0; i < NSTAGE - 1; i++) {
        z_issue(sb + i * ZSTG, bm, i, t);
        cp_commit();
    }

    for (int i = 0; i < NIT_MAIN; i++) {
        cp_wait<NSTAGE - 2>();
        __syncthreads();
        const uint32_t stg = sb + (i % NSTAGE) * ZSTG;
        const uint32_t sXhi = stg, sXlo = stg + ZXT;
        const uint32_t sAhi = stg + 2 * ZXT, sAlo = stg + 2 * ZXT + ZAT;
#pragma unroll
        for (int ks = 0; ks < 2; ks++) {
            uint32_t ahi[4][4], alo[4][4], bh[4], bl[4];
            const int arow = wm * 64 + (lane & 15);
            const int acol = ks * 16 + (lane >> 4) * 8;
#pragma unroll
            for (int mt = 0; mt < 4; mt++) {
                const uint32_t off = (uint32_t)((arow + mt * 16) * PADK + acol) * 2;
                ldsm4(ahi[mt], sXhi + off);
                ldsm4(alo[mt], sXlo + off);
            }
            const int brow = wn * 16 + ((lane >> 4) << 3) + (lane & 7);
            const int bcol = ks * 16 + (((lane >> 3) & 1) << 3);
            const uint32_t boff = (uint32_t)(brow * PADK + bcol) * 2;
            ldsm4(bh, sAhi + boff);
            ldsm4(bl, sAlo + boff);
#pragma unroll
            for (int mt = 0; mt < 4; mt++)
#pragma unroll
                for (int nt = 0; nt < 2; nt++) {
                    mma_bf16(acc[mt][nt], ahi[mt], &bh[nt * 2]);
                    mma_bf16(acc[mt][nt], alo[mt], &bh[nt * 2]);
                    mma_bf16(acc[mt][nt], ahi[mt], &bl[nt * 2]);
                }
        }
        if (i + NSTAGE - 1 < NIT_MAIN)
            z_issue(sb + ((i + NSTAGE - 1) % NSTAGE) * ZSTG, bm, i + NSTAGE - 1, t);
        cp_commit();
    }

    // stash z into smem (reuse stage memory), then top-k mask + bf16 split
    __syncthreads();                        // everyone done reading stages
    float* zbuf = (float*)zsm;              // [128][ZPAD]
    const int gr = lane >> 2, gc = (lane & 3) * 2;
#pragma unroll
    for (int mt = 0; mt < 4; mt++)
#pragma unroll
        for (int nt = 0; nt < 2; nt++) {
            int row = wm * 64 + mt * 16 + gr;
            int col = wn * 16 + nt * 8 + gc;
            *(float2*)(zbuf + row * ZPAD + col) = make_float2(acc[mt][nt][0], acc[mt][nt][1]);
            *(float2*)(zbuf + (row + 8) * ZPAD + col) = make_float2(acc[mt][nt][2], acc[mt][nt][3]);
        }
    __syncthreads();

    const int kkeep = *kp;
#pragma unroll
    for (int e = 0; e < 32; e++) {
        int idx = e * 256 + t;              // 128*64 entries
        int row = idx >> 6, rr = idx & 63;
        float zv = zbuf[row * ZPAD + rr];
        float az = fabsf(zv);
        int cnt = 0;
#pragma unroll
        for (int j = 0; j < 64; j++) cnt += (fabsf(zbuf[row * ZPAD + j]) > az) ? 1 : 0;
        float zm = (cnt < kkeep) ? zv : 0.0f;
        __nv_bfloat16 h = __float2bfloat16(zm);
        float lo = zm - __bfloat162float(h);
        size_t gi = (size_t)(bm + row) * RNK + rr;
        g_Zhi[gi] = h;
        g_Zlo[gi] = __float2bfloat16(lo);
    }
}

// ================= main GEMM: out = x@W^T + b + z_sparse@(B*SCALE)^T =================
__device__ __forceinline__ void issue_stage(uint32_t stg, int bm, int bn, int i, int t) {
    const __nv_bfloat16 *pah, *pal, *pbh, *pbl;
    int stride;
    if (i < NIT_MAIN) {
        const int kk = i * BK;
        pah = g_Xhi + (size_t)bm * DIN + kk;
        pal = g_Xlo + (size_t)bm * DIN + kk;
        pbh = g_Whi + (size_t)bn * DIN + kk;
        pbl = g_Wlo + (size_t)bn * DIN + kk;
        stride = DIN;
    } else {
        const int kk = (i - NIT_MAIN) * BK;
        pah = g_Zhi + (size_t)bm * RNK + kk;
        pal = g_Zlo + (size_t)bm * RNK + kk;
        pbh = g_Bhi + (size_t)bn * RNK + kk;
        pbl = g_Blo + (size_t)bn * RNK + kk;
        stride = RNK;
    }
    // X tiles: 128 rows x 4 parts
#pragma unroll
    for (int j = 0; j < 2; j++) {
        const int idx = t + j * 256;
        const int row = idx >> 2, part = idx & 3;
        const uint32_t d = (uint32_t)(row * PADK + part * 8) * 2;
        const size_t s = (size_t)row * stride + part * 8;
        cp16s(stg + d,            pah + s);
        cp16s(stg + XT_BYTES + d, pal + s);
    }
    // W tiles: 256 rows x 4 parts
#pragma unroll
    for (int j = 0; j < 4; j++) {
        const int idx = t + j * 256;
        const int row = idx >> 2, part = idx & 3;
        const uint32_t d = (uint32_t)(row * PADK + part * 8) * 2;
        const size_t s = (size_t)row * stride + part * 8;
        cp16s(stg + 2 * XT_BYTES + d,            pbh + s);
        cp16s(stg + 2 * XT_BYTES + WT_BYTES + d, pbl + s);
    }
}

__global__ __launch_bounds__(256, 1)
void gemm_kernel(const float* __restrict__ bias, float* __restrict__ out) {
    extern __shared__ __nv_bfloat16 smem[];
    const uint32_t sb = sptr(smem);
    const int t = threadIdx.x;
    const int warp = t >> 5, lane = t & 31;
    const int wm = warp & 1, wn = warp >> 1;   // 2x4 grid -> 64x64 warp tile
    const int bm = (int)blockIdx.y * BM, bn = (int)blockIdx.x * BN;

    float acc[4][8][4];
#pragma unroll
    for (int a = 0; a < 4; a++)
#pragma unroll
        for (int b = 0; b < 8; b++)
#pragma unroll
            for (int c = 0; c < 4; c++) acc[a][b][c] = 0.0f;

#pragma unroll
    for (int i = 0; i < NSTAGE - 1; i++) {
        issue_stage(sb + i * STG_BYTES, bm, bn, i, t);
        cp_commit();
    }

    for (int i = 0; i < NIT; i++) {
        cp_wait<NSTAGE - 2>();
        __syncthreads();
        const uint32_t stg = sb + (i % NSTAGE) * STG_BYTES;
        const uint32_t sXhi = stg, sXlo = stg + XT_BYTES;
        const uint32_t sWhi = stg + 2 * XT_BYTES, sWlo = sWhi + WT_BYTES;
#pragma unroll
        for (int ks = 0; ks < 2; ks++) {
            uint32_t ahi[4][4], alo[4][4], bfr[4][4];
            const int arow = wm * 64 + (lane & 15);
            const int acol = ks * 16 + (lane >> 4) * 8;
#pragma unroll
            for (int mt = 0; mt < 4; mt++) {
                const uint32_t off = (uint32_t)((arow + mt * 16) * PADK + acol) * 2;
                ldsm4(ahi[mt], sXhi + off);
                ldsm4(alo[mt], sXlo + off);
            }
            const int brow0 = wn * 64 + ((lane >> 4) << 3) + (lane & 7);
            const int bcol = ks * 16 + (((lane >> 3) & 1) << 3);
            // ---- B-hi: xhi*Whi and xlo*Whi ----
#pragma unroll
            for (int np = 0; np < 4; np++) {
                const uint32_t off = (uint32_t)((brow0 + np * 16) * PADK + bcol) * 2;
                ldsm4(bfr[np], sWhi + off);
            }
#pragma unroll
            for (int mt = 0; mt < 4; mt++)
#pragma unroll
                for (int nt = 0; nt < 8; nt++) {
                    const uint32_t* b = &bfr[nt >> 1][(nt & 1) * 2];
                    mma_bf16(acc[mt][nt], ahi[mt], b);
                    mma_bf16(acc[mt][nt], alo[mt], b);
                }
            // ---- B-lo: xhi*Wlo ----
#pragma unroll
            for (int np = 0; np < 4; np++) {
                const uint32_t off = (uint32_t)((brow0 + np * 16) * PADK + bcol) * 2;
                ldsm4(bfr[np], sWlo + off);
            }
#pragma unroll
            for (int mt = 0; mt < 4; mt++)
#pragma unroll
                for (int nt = 0; nt < 8; nt++)
                    mma_bf16(acc[mt][nt], ahi[mt], &bfr[nt >> 1][(nt & 1) * 2]);
        }
        if (i + NSTAGE - 1 < NIT)
            issue_stage(sb + ((i + NSTAGE - 1) % NSTAGE) * STG_BYTES, bm, bn,
                        i + NSTAGE - 1, t);
        cp_commit();
    }

    // epilogue: + bias, store fp32
    const int gr = lane >> 2, gc = (lane & 3) * 2;
#pragma unroll
    for (int mt = 0; mt < 4; mt++) {
#pragma unroll
        for (int nt = 0; nt < 8; nt++) {
            int row = bm + wm * 64 + mt * 16 + gr;
            int col = bn + wn * 64 + nt * 8 + gc;
            float2 bv = *(const float2*)(bias + col);
            float2 o0, o1;
            o0.x = acc[mt][nt][0] + bv.x;
            o0.y = acc[mt][nt][1] + bv.y;
            o1.x = acc[mt][nt][2] + bv.x;
            o1.y = acc[mt][nt][3] + bv.y;
            *(float2*)(out + (size_t)row * DOUT + col) = o0;
            *(float2*)(out + (size_t)(row + 8) * DOUT + col) = o1;
        }
    }
}

// ---------------- launch ----------------
extern "C" void kernel_launch(void* const* d_in, const int* in_sizes, int n_in,
                              void* d_out, int out_size) {
    const float* x = (const float*)d_in[0];
    const float* W = (const float*)d_in[1];
    const float* b = (const float*)d_in[2];
    const float* A = (const float*)d_in[3];
    const float* B = (const float*)d_in[4];
    const int*   k = (const int*)d_in[5];
    float* out = (float*)d_out;
    (void)in_sizes; (void)n_in; (void)out_size;

    conv_w_kernel<<<(DOUT * DIN) / (256 * 8), 256>>>(W);
    conv_x_kernel<<<(int)(((size_t)MROWS * DIN) / (256 * 8)), 256>>>(x);
    conv_a_kernel<<<(RNK * DIN) / (256 * 8), 256>>>(A);
    conv_b_kernel<<<(DOUT * RNK) / (256 * 8), 256>>>(B, 2.0f /* ALPHA/R */);

    // z = x@A^T (HMMA, split-bf16), top-k mask, split to bf16 hi/lo
    cudaFuncSetAttribute(z_mma_topk_kernel, cudaFuncAttributeMaxDynamicSharedMemorySize,
                         NSTAGE * ZSTG);
    z_mma_topk_kernel<<<MROWS / BM, 256, NSTAGE * ZSTG>>>(k);

    // fused GEMM
    cudaFuncSetAttribute(gemm_kernel, cudaFuncAttributeMaxDynamicSharedMemorySize,
                         NSTAGE * STG_BYTES);
    gemm_kernel<<<dim3(DOUT / BN, MROWS / BM), 256, NSTAGE * STG_BYTES>>>(b, out);
}